// round 5
// baseline (speedup 1.0000x reference)
#include <cuda_runtime.h>
#include <cuda_bf16.h>

// Problem constants
#define H_  32
#define W_  32
#define C_  512
#define CLS_ 1000
#define R_  64
#define B_  128

#define MROWS (B_ * C_)        // 65536
#define KDIM  (W_ * H_)        // 1024

// GEMM tiling
#define BM 128
#define BN 64
#define BK 32

// Scratch (static device memory — no allocations allowed)
__device__ float g_M[KDIM * R_];          // 1024 x 64  merged U2*U1
__device__ float g_G1[(size_t)MROWS * R_]; // 65536 x 64 (16 MB)
__device__ float g_t3[B_ * R_];           // 128 x 64

// ---------------------------------------------------------------------------
// Kernel 0: M[w*32+h, r] = U2[w,r] * U1[h,r]
// ---------------------------------------------------------------------------
__global__ void build_M_kernel(const float* __restrict__ U1,
                               const float* __restrict__ U2) {
    int idx = blockIdx.x * blockDim.x + threadIdx.x;   // 0 .. 65535
    int wh = idx / R_;
    int r  = idx % R_;
    int w  = wh / H_;
    int h  = wh % H_;
    g_M[idx] = U2[w * R_ + r] * U1[h * R_ + r];
}

// ---------------------------------------------------------------------------
// Kernel 1: G1 = x(65536,1024) @ M(1024,64)   — the 4.3 GMAC GEMM
// ---------------------------------------------------------------------------
__global__ __launch_bounds__(256) void gemm_xM_kernel(const float* __restrict__ A) {
    __shared__ float As[BK][BM + 4];   // k-major, padded (avoids LDS conflicts)
    __shared__ float Bs[BK][BN];

    const int tid = threadIdx.x;
    const int m0  = blockIdx.x * BM;

    // compute mapping: 16 n-groups x 16 m-groups, thread tile 8m x 4n
    const int tn = tid & 15;     // 0..15  -> cols tn*4 .. tn*4+3
    const int tm = tid >> 4;     // 0..15  -> rows tm*8 .. tm*8+7

    // A global-load mapping: 8 threads per row (4 floats each), 32 rows/pass
    const int ar = tid >> 3;         // 0..31 row within pass
    const int ak = (tid & 7) * 4;    // k offset 0,4,...,28

    float acc[8][4];
#pragma unroll
    for (int i = 0; i < 8; i++)
#pragma unroll
        for (int j = 0; j < 4; j++) acc[i][j] = 0.0f;

    for (int k0 = 0; k0 < KDIM; k0 += BK) {
        // --- load A tile (128 x 32), store transposed into smem ---
#pragma unroll
        for (int p = 0; p < 4; p++) {
            int m = p * 32 + ar;
            const float4 v = *(const float4*)(A + (long)(m0 + m) * KDIM + k0 + ak);
            As[ak + 0][m] = v.x;
            As[ak + 1][m] = v.y;
            As[ak + 2][m] = v.z;
            As[ak + 3][m] = v.w;
        }
        // --- load B tile (32 x 64) ---
#pragma unroll
        for (int p = 0; p < 2; p++) {
            int idx = p * 256 + tid;         // 0..511 float4 slots
            int kk  = idx >> 4;              // 0..31
            int nn  = (idx & 15) * 4;        // 0..60
            *(float4*)&Bs[kk][nn] = *(const float4*)(g_M + (k0 + kk) * BN + nn);
        }
        __syncthreads();

#pragma unroll
        for (int k = 0; k < BK; k++) {
            float a[8], b[4];
            *(float4*)&a[0] = *(const float4*)&As[k][tm * 8];
            *(float4*)&a[4] = *(const float4*)&As[k][tm * 8 + 4];
            *(float4*)&b[0] = *(const float4*)&Bs[k][tn * 4];
#pragma unroll
            for (int i = 0; i < 8; i++)
#pragma unroll
                for (int j = 0; j < 4; j++)
                    acc[i][j] = fmaf(a[i], b[j], acc[i][j]);
        }
        __syncthreads();
    }

#pragma unroll
    for (int i = 0; i < 8; i++) {
        long m = m0 + tm * 8 + i;
        *(float4*)(g_G1 + m * R_ + tn * 4) = *(float4*)&acc[i][0];
    }
}

// ---------------------------------------------------------------------------
// Kernel 2: t3[b,r] = sum_c G1[b*512+c, r] * U3[c,r]
// ---------------------------------------------------------------------------
__global__ __launch_bounds__(256) void reduce_c_kernel(const float* __restrict__ U3) {
    const int b = blockIdx.x;          // 0..127
    const int r = threadIdx.x & 63;
    const int q = threadIdx.x >> 6;    // 0..3
    float s = 0.0f;
    for (int c = q; c < C_; c += 4)
        s = fmaf(g_G1[((long)(b * C_ + c)) * R_ + r], U3[c * R_ + r], s);
    __shared__ float red[4][R_];
    red[q][r] = s;
    __syncthreads();
    if (q == 0)
        g_t3[b * R_ + r] = red[0][r] + red[1][r] + red[2][r] + red[3][r];
}

// ---------------------------------------------------------------------------
// Kernel 3: out[b,cls] = sum_r t3[b,r] * lam[r] * U4[cls,r]
// ---------------------------------------------------------------------------
__global__ __launch_bounds__(128) void out_kernel(const float* __restrict__ lam,
                                                  const float* __restrict__ U4,
                                                  float* __restrict__ out) {
    const int cls = blockIdx.x;        // 0..999
    const int b   = threadIdx.x;       // 0..127
    __shared__ float u[R_];
    if (threadIdx.x < R_)
        u[threadIdx.x] = U4[cls * R_ + threadIdx.x] * lam[threadIdx.x];
    __syncthreads();
    float s = 0.0f;
#pragma unroll
    for (int r = 0; r < R_; r++)
        s = fmaf(g_t3[b * R_ + r], u[r], s);
    out[b * CLS_ + cls] = s;
}

// ---------------------------------------------------------------------------
extern "C" void kernel_launch(void* const* d_in, const int* in_sizes, int n_in,
                              void* d_out, int out_size) {
    const float* x   = (const float*)d_in[0];   // (B, C, W, H)
    const float* U1  = (const float*)d_in[1];   // (H, R)
    const float* U2  = (const float*)d_in[2];   // (W, R)
    const float* U3  = (const float*)d_in[3];   // (C, R)
    const float* U4  = (const float*)d_in[4];   // (CLS, R)
    const float* lam = (const float*)d_in[5];   // (R,)
    float* out = (float*)d_out;                 // (B, CLS)

    build_M_kernel<<<(KDIM * R_) / 256, 256>>>(U1, U2);
    gemm_xM_kernel<<<MROWS / BM, 256>>>(x);
    reduce_c_kernel<<<B_, 256>>>(U3);
    out_kernel<<<CLS_, 128>>>(lam, U4, out);
}

// round 7
// speedup vs baseline: 2.3806x; 2.3806x over previous
#include <cuda_runtime.h>
#include <cuda_bf16.h>
#include <cstdint>

#define H_   32
#define W_   32
#define C_   512
#define CLS_ 1000
#define R_   64
#define B_   128
#define MROWS (B_ * C_)      // 65536
#define KDIM  1024           // W*H

// ---- GEMM tiling ----
#define TILE_M   128
#define KCHUNK   64          // bf16 per row = 128 B (one swizzle atom row)
#define NCHUNKS  16
// smem layout (bytes): Ah 16K | Al 16K | Bh 8K | Bl 8K  = 48K
#define AH_OFF   0
#define AL_OFF   16384
#define BH_OFF   32768
#define BL_OFF   40960
#define SMEM_DYN 49152

#define SW(o) ((o) ^ (((o) >> 3) & 0x70))

// ---- static device scratch (no allocations allowed) ----
__device__ __align__(16) __nv_bfloat16 g_Mh[R_ * KDIM];   // [r][k] hi  (col-major B)
__device__ __align__(16) __nv_bfloat16 g_Ml[R_ * KDIM];   // [r][k] lo
__device__ float g_part[512 * R_];                        // per-CTA partials

// ===========================================================================
// PTX helpers — baseline sm_80+ instructions only (no sm_103a features)
// ===========================================================================
__device__ __forceinline__ uint32_t smem_u32(const void* p) {
    uint32_t a;
    asm("{ .reg .u64 t; cvta.to.shared.u64 t, %1; cvt.u32.u64 %0, t; }"
        : "=r"(a) : "l"(p));
    return a;
}
__device__ __forceinline__ void sts64(uint32_t a, uint32_t x, uint32_t y) {
    asm volatile("st.shared.v2.b32 [%0], {%1,%2};" :: "r"(a), "r"(x), "r"(y));
}
__device__ __forceinline__ void sts128(uint32_t a, uint4 v) {
    asm volatile("st.shared.v4.b32 [%0], {%1,%2,%3,%4};"
                 :: "r"(a), "r"(v.x), "r"(v.y), "r"(v.z), "r"(v.w));
}
__device__ __forceinline__ void ldm4(uint32_t* r, uint32_t addr) {
    asm volatile("ldmatrix.sync.aligned.m8n8.x4.shared.b16 {%0,%1,%2,%3}, [%4];"
                 : "=r"(r[0]), "=r"(r[1]), "=r"(r[2]), "=r"(r[3]) : "r"(addr));
}
__device__ __forceinline__ void mma16816(float* c, const uint32_t* a, const uint32_t* b) {
    asm volatile(
        "mma.sync.aligned.m16n8k16.row.col.f32.bf16.bf16.f32 "
        "{%0,%1,%2,%3}, {%4,%5,%6,%7}, {%8,%9}, {%0,%1,%2,%3};"
        : "+f"(c[0]), "+f"(c[1]), "+f"(c[2]), "+f"(c[3])
        : "r"(a[0]), "r"(a[1]), "r"(a[2]), "r"(a[3]), "r"(b[0]), "r"(b[1]));
}

// ===========================================================================
// Kernel 0: Mh/Ml[r][k] = bf16 hi/lo split of U2[w,r]*U1[h,r],  k = w*32+h
// ===========================================================================
__global__ void build_M(const float* __restrict__ U1, const float* __restrict__ U2) {
    int idx = blockIdx.x * 256 + threadIdx.x;   // = r*1024 + k
    int r = idx >> 10, k = idx & 1023;
    int w = k >> 5, h = k & 31;
    float v = U2[w * R_ + r] * U1[h * R_ + r];
    __nv_bfloat16 hi = __float2bfloat16_rn(v);
    g_Mh[idx] = hi;
    g_Ml[idx] = __float2bfloat16_rn(v - __bfloat162float(hi));
}

// ===========================================================================
// Kernel 1: bf16-split mma.sync GEMM (128x64 tile, K=1024) + fused U3 reduce
//   grid 512, block 256 (8 warps: 4 m-groups x 2 n-groups), dyn smem 48K
// ===========================================================================
__global__ __launch_bounds__(256, 2) void gemm_k(const float* __restrict__ x,
                                                 const float* __restrict__ U3) {
    extern __shared__ char dsm[];
    __shared__ float s_red[4][R_];

    const int tid  = threadIdx.x;
    const int wid  = tid >> 5;
    const int lane = tid & 31;
    const int m_warp = (wid >> 1) * 32;   // 0,32,64,96
    const int n_warp = (wid & 1) * 32;    // 0,32
    const long m0 = (long)blockIdx.x * TILE_M;

    const uint32_t sb = smem_u32(dsm);

    float acc[2][4][4];
#pragma unroll
    for (int i = 0; i < 2; i++)
#pragma unroll
        for (int j = 0; j < 4; j++)
#pragma unroll
            for (int e = 0; e < 4; e++) acc[i][j][e] = 0.0f;

    for (int s = 0; s < NCHUNKS; s++) {
        const int k0 = s * KCHUNK;

        // ---- A tile: 128 rows x 64 fp32 -> bf16 hi/lo, swizzled smem ----
        const float* xg = x + m0 * KDIM + k0;
#pragma unroll
        for (int it = 0; it < 8; it++) {
            int idx = tid + it * 256;
            int row = idx >> 4, f = idx & 15;
            float4 v = *(const float4*)(xg + (long)row * KDIM + f * 4);
            __nv_bfloat16 h0 = __float2bfloat16_rn(v.x);
            __nv_bfloat16 h1 = __float2bfloat16_rn(v.y);
            __nv_bfloat16 h2 = __float2bfloat16_rn(v.z);
            __nv_bfloat16 h3 = __float2bfloat16_rn(v.w);
            __nv_bfloat16 l0 = __float2bfloat16_rn(v.x - __bfloat162float(h0));
            __nv_bfloat16 l1 = __float2bfloat16_rn(v.y - __bfloat162float(h1));
            __nv_bfloat16 l2 = __float2bfloat16_rn(v.z - __bfloat162float(h2));
            __nv_bfloat16 l3 = __float2bfloat16_rn(v.w - __bfloat162float(h3));
            uint32_t hA = (uint32_t)__bfloat16_as_ushort(h0) | ((uint32_t)__bfloat16_as_ushort(h1) << 16);
            uint32_t hB = (uint32_t)__bfloat16_as_ushort(h2) | ((uint32_t)__bfloat16_as_ushort(h3) << 16);
            uint32_t lA = (uint32_t)__bfloat16_as_ushort(l0) | ((uint32_t)__bfloat16_as_ushort(l1) << 16);
            uint32_t lB = (uint32_t)__bfloat16_as_ushort(l2) | ((uint32_t)__bfloat16_as_ushort(l3) << 16);
            uint32_t off = row * 128 + f * 8;
            uint32_t sw  = SW(off);
            sts64(sb + AH_OFF + sw, hA, hB);
            sts64(sb + AL_OFF + sw, lA, lB);
        }
        // ---- B tiles: 64 n-rows x 128 B (hi, lo) ----
#pragma unroll
        for (int it = 0; it < 2; it++) {
            int idx = tid + it * 256;
            int n = idx >> 3, j = idx & 7;
            long boff = (long)n * 2048 + k0 * 2 + j * 16;
            uint4 vh = *(const uint4*)((const char*)g_Mh + boff);
            uint4 vl = *(const uint4*)((const char*)g_Ml + boff);
            uint32_t sw = SW((uint32_t)(n * 128 + j * 16));
            sts128(sb + BH_OFF + sw, vh);
            sts128(sb + BL_OFF + sw, vl);
        }
        __syncthreads();

        // ---- compute: 4 k16-steps, 3 bf16 products each ----
#pragma unroll
        for (int kk = 0; kk < 4; kk++) {
            uint32_t ah[2][4], al[2][4], bh[2][4], bl[2][4];
#pragma unroll
            for (int mi = 0; mi < 2; mi++) {
                uint32_t row = m_warp + mi * 16 + (lane & 15);
                uint32_t kb  = kk * 32 + (lane >> 4) * 16;
                uint32_t off = SW(row * 128 + kb);
                ldm4(ah[mi], sb + AH_OFF + off);
                ldm4(al[mi], sb + AL_OFF + off);
            }
#pragma unroll
            for (int nq = 0; nq < 2; nq++) {
                uint32_t g = lane >> 3;
                uint32_t n = n_warp + nq * 16 + ((g >> 1) << 3) + (lane & 7);
                uint32_t kb = kk * 32 + (g & 1) * 16;
                uint32_t off = SW(n * 128 + kb);
                ldm4(bh[nq], sb + BH_OFF + off);
                ldm4(bl[nq], sb + BL_OFF + off);
            }
#pragma unroll
            for (int mi = 0; mi < 2; mi++)
#pragma unroll
                for (int nj = 0; nj < 4; nj++) {
                    const uint32_t* B1 = &bh[nj >> 1][(nj & 1) * 2];
                    const uint32_t* B2 = &bl[nj >> 1][(nj & 1) * 2];
                    mma16816(acc[mi][nj], ah[mi], B1);   // hi*hi
                    mma16816(acc[mi][nj], al[mi], B1);   // lo*hi
                    mma16816(acc[mi][nj], ah[mi], B2);   // hi*lo
                }
        }
        __syncthreads();
    }

    // ---- epilogue: scale by U3[c,r], reduce 128 rows -> 64 partials ----
    float* s_u3 = (float*)dsm;                         // reuse 32 KB
    const int c_base = (blockIdx.x & 3) * 128;
#pragma unroll
    for (int it = 0; it < 32; it++) {
        int idx = tid + it * 256;                      // 0..8191
        s_u3[idx] = U3[c_base * R_ + idx];
    }
    __syncthreads();

    float p[8];
#pragma unroll
    for (int j = 0; j < 8; j++) p[j] = 0.0f;
#pragma unroll
    for (int mi = 0; mi < 2; mi++)
#pragma unroll
        for (int pr = 0; pr < 2; pr++) {
            int rowl = m_warp + mi * 16 + pr * 8 + (lane >> 2);
            const float* w = s_u3 + rowl * R_;
#pragma unroll
            for (int nj = 0; nj < 4; nj++) {
                int col = n_warp + nj * 8 + (lane & 3) * 2;
                p[nj * 2 + 0] = fmaf(acc[mi][nj][pr * 2 + 0], w[col],     p[nj * 2 + 0]);
                p[nj * 2 + 1] = fmaf(acc[mi][nj][pr * 2 + 1], w[col + 1], p[nj * 2 + 1]);
            }
        }
#pragma unroll
    for (int o = 4; o < 32; o <<= 1)
#pragma unroll
        for (int j = 0; j < 8; j++)
            p[j] += __shfl_xor_sync(0xffffffffu, p[j], o);

    if (lane < 4) {
#pragma unroll
        for (int nj = 0; nj < 4; nj++) {
            int col = n_warp + nj * 8 + lane * 2;
            s_red[wid >> 1][col]     = p[nj * 2 + 0];
            s_red[wid >> 1][col + 1] = p[nj * 2 + 1];
        }
    }
    __syncthreads();
    if (tid < R_)
        g_part[blockIdx.x * R_ + tid] =
            s_red[0][tid] + s_red[1][tid] + s_red[2][tid] + s_red[3][tid];
}

// ===========================================================================
// Kernel 2: out[b,cls] = sum_r (sum_j part[4b+j,r]) * lam[r] * U4[cls,r]
// ===========================================================================
__global__ __launch_bounds__(256) void out_k(const float* __restrict__ lam,
                                             const float* __restrict__ U4,
                                             float* __restrict__ out) {
    const int b = blockIdx.x;
    const int tid = threadIdx.x;
    __shared__ float u[R_];
    if (tid < R_) {
        float s = g_part[(b * 4 + 0) * R_ + tid] + g_part[(b * 4 + 1) * R_ + tid]
                + g_part[(b * 4 + 2) * R_ + tid] + g_part[(b * 4 + 3) * R_ + tid];
        u[tid] = s * lam[tid];
    }
    __syncthreads();
    for (int cls = tid; cls < CLS_; cls += 256) {
        const float4* up = (const float4*)(U4 + cls * R_);
        float s = 0.0f;
#pragma unroll
        for (int j = 0; j < 16; j++) {
            float4 v = up[j];
            s = fmaf(u[j * 4 + 0], v.x, s);
            s = fmaf(u[j * 4 + 1], v.y, s);
            s = fmaf(u[j * 4 + 2], v.z, s);
            s = fmaf(u[j * 4 + 3], v.w, s);
        }
        out[b * CLS_ + cls] = s;
    }
}

// ===========================================================================
extern "C" void kernel_launch(void* const* d_in, const int* in_sizes, int n_in,
                              void* d_out, int out_size) {
    const float* x   = (const float*)d_in[0];   // (B, C, W, H)
    const float* U1  = (const float*)d_in[1];   // (H, R)
    const float* U2  = (const float*)d_in[2];   // (W, R)
    const float* U3  = (const float*)d_in[3];   // (C, R)
    const float* U4  = (const float*)d_in[4];   // (CLS, R)
    const float* lam = (const float*)d_in[5];   // (R,)
    float* out = (float*)d_out;                 // (B, CLS)

    cudaFuncSetAttribute(gemm_k, cudaFuncAttributeMaxDynamicSharedMemorySize, SMEM_DYN);

    build_M<<<256, 256>>>(U1, U2);
    gemm_k<<<MROWS / TILE_M, 256, SMEM_DYN>>>(x, U3);
    out_k<<<B_, 256>>>(lam, U4, out);
}

// round 8
// speedup vs baseline: 2.6742x; 1.1233x over previous
#include <cuda_runtime.h>
#include <cuda_bf16.h>
#include <cstdint>

#define H_   32
#define W_   32
#define C_   512
#define CLS_ 1000
#define R_   64
#define B_   128
#define MROWS (B_ * C_)      // 65536
#define KDIM  1024           // W*H

// ---- GEMM tiling ----
#define TILE_M   128
#define KCHUNK   64          // bf16 per row = 128 B (one swizzle atom row)
#define NCHUNKS  16
// per-stage smem layout (bytes): Ah 16K | Al 16K | Bh 8K | Bl 8K = 48K, x2 stages
#define AH_OFF   0
#define AL_OFF   16384
#define BH_OFF   32768
#define BL_OFF   40960
#define STAGE    49152
#define SMEM_DYN (2 * STAGE)   // 96 KB

#define SW(o) ((o) ^ (((o) >> 3) & 0x70))

// ---- static device scratch (no allocations allowed) ----
__device__ __align__(16) __nv_bfloat16 g_Mh[R_ * KDIM];   // [r][k] hi
__device__ __align__(16) __nv_bfloat16 g_Ml[R_ * KDIM];   // [r][k] lo
__device__ float g_part[512 * R_];                        // per-CTA partials

// ===========================================================================
// PTX helpers — sm_80+ baseline only
// ===========================================================================
__device__ __forceinline__ uint32_t smem_u32(const void* p) {
    uint32_t a;
    asm("{ .reg .u64 t; cvta.to.shared.u64 t, %1; cvt.u32.u64 %0, t; }"
        : "=r"(a) : "l"(p));
    return a;
}
__device__ __forceinline__ void sts64(uint32_t a, uint32_t x, uint32_t y) {
    asm volatile("st.shared.v2.b32 [%0], {%1,%2};" :: "r"(a), "r"(x), "r"(y));
}
__device__ __forceinline__ void cpasync16(uint32_t dst, const void* src) {
    asm volatile("cp.async.cg.shared.global [%0], [%1], 16;"
                 :: "r"(dst), "l"(src));
}
__device__ __forceinline__ void cp_commit() {
    asm volatile("cp.async.commit_group;");
}
template <int N>
__device__ __forceinline__ void cp_wait() {
    asm volatile("cp.async.wait_group %0;" :: "n"(N));
}
__device__ __forceinline__ void ldm4(uint32_t* r, uint32_t addr) {
    asm volatile("ldmatrix.sync.aligned.m8n8.x4.shared.b16 {%0,%1,%2,%3}, [%4];"
                 : "=r"(r[0]), "=r"(r[1]), "=r"(r[2]), "=r"(r[3]) : "r"(addr));
}
__device__ __forceinline__ void mma16816(float* c, const uint32_t* a, const uint32_t* b) {
    asm volatile(
        "mma.sync.aligned.m16n8k16.row.col.f32.bf16.bf16.f32 "
        "{%0,%1,%2,%3}, {%4,%5,%6,%7}, {%8,%9}, {%0,%1,%2,%3};"
        : "+f"(c[0]), "+f"(c[1]), "+f"(c[2]), "+f"(c[3])
        : "r"(a[0]), "r"(a[1]), "r"(a[2]), "r"(a[3]), "r"(b[0]), "r"(b[1]));
}

// ===========================================================================
// Kernel 0: Mh/Ml[r][k] = bf16 hi/lo split of U2[w,r]*U1[h,r],  k = w*32+h
//   grid 64 (one block per r), block 1024 (one thread per k) — coalesced
// ===========================================================================
__global__ __launch_bounds__(1024) void build_M(const float* __restrict__ U1,
                                                const float* __restrict__ U2) {
    __shared__ float su1[32], su2[32];
    const int r = blockIdx.x;
    if (threadIdx.x < 32)       su1[threadIdx.x]      = U1[threadIdx.x * R_ + r];
    else if (threadIdx.x < 64)  su2[threadIdx.x - 32] = U2[(threadIdx.x - 32) * R_ + r];
    __syncthreads();
    const int k = threadIdx.x;
    float v = su2[k >> 5] * su1[k & 31];
    __nv_bfloat16 hi = __float2bfloat16_rn(v);
    g_Mh[r * KDIM + k] = hi;
    g_Ml[r * KDIM + k] = __float2bfloat16_rn(v - __bfloat162float(hi));
}

// ===========================================================================
// Kernel 1: pipelined bf16-split mma.sync GEMM + fused U3 row-reduce
//   grid 512, block 256 (8 warps: 4 m-groups x 2 n-groups), dyn smem 96K
// ===========================================================================
__global__ __launch_bounds__(256, 2) void gemm_k(const float* __restrict__ x,
                                                 const float* __restrict__ U3) {
    extern __shared__ char dsm[];
    __shared__ float s_red[4][R_];

    const int tid  = threadIdx.x;
    const int wid  = tid >> 5;
    const int lane = tid & 31;
    const int m_warp = (wid >> 1) * 32;   // 0,32,64,96
    const int n_warp = (wid & 1) * 32;    // 0,32
    const long m0 = (long)blockIdx.x * TILE_M;

    const uint32_t sb = smem_u32(dsm);

    // B cp.async source/dest mapping (2 slots of 2 per thread: hi, lo)
    const int bn = tid >> 3;            // 0..31  (row pairs: handles n=bn and n=bn+32)
    const int bj = tid & 7;             // 16B slot within 128B row

    // A prefetch mapping: row = rb + it*16, cols f*4..f*4+3
    const int rb = tid >> 4;            // 0..15
    const int f  = tid & 15;            // 0..15

    float acc[2][4][4];
#pragma unroll
    for (int i = 0; i < 2; i++)
#pragma unroll
        for (int j = 0; j < 4; j++)
#pragma unroll
            for (int e = 0; e < 4; e++) acc[i][j][e] = 0.0f;

    // ---- prologue: B chunk 0 via cp.async, A chunk 0 into registers ----
    {
        const uint32_t bs = sb;  // stage 0
#pragma unroll
        for (int it = 0; it < 2; it++) {
            int n = bn + it * 32;
            long go = (long)n * 2048 + bj * 16;      // k0 = 0
            uint32_t sw = SW((uint32_t)(n * 128 + bj * 16));
            cpasync16(bs + BH_OFF + sw, (const char*)g_Mh + go);
            cpasync16(bs + BL_OFF + sw, (const char*)g_Ml + go);
        }
        cp_commit();
    }
    float4 pf[8];
    {
        const float* xg = x + m0 * KDIM;             // k0 = 0
#pragma unroll
        for (int it = 0; it < 8; it++)
            pf[it] = *(const float4*)(xg + (long)(rb + it * 16) * KDIM + f * 4);
    }

    for (int s = 0; s < NCHUNKS; s++) {
        const uint32_t bb = sb + (uint32_t)(s & 1) * STAGE;
        const uint32_t nb = sb + (uint32_t)((s + 1) & 1) * STAGE;

        // ---- issue B cp.async for chunk s+1 ----
        if (s < NCHUNKS - 1) {
            const int k1 = (s + 1) * KCHUNK;
#pragma unroll
            for (int it = 0; it < 2; it++) {
                int n = bn + it * 32;
                long go = (long)n * 2048 + k1 * 2 + bj * 16;
                uint32_t sw = SW((uint32_t)(n * 128 + bj * 16));
                cpasync16(nb + BH_OFF + sw, (const char*)g_Mh + go);
                cpasync16(nb + BL_OFF + sw, (const char*)g_Ml + go);
            }
            cp_commit();
        }

        // ---- convert prefetched A regs -> bf16 hi/lo swizzled smem ----
#pragma unroll
        for (int it = 0; it < 8; it++) {
            float4 v = pf[it];
            __nv_bfloat16 h0 = __float2bfloat16_rn(v.x);
            __nv_bfloat16 h1 = __float2bfloat16_rn(v.y);
            __nv_bfloat16 h2 = __float2bfloat16_rn(v.z);
            __nv_bfloat16 h3 = __float2bfloat16_rn(v.w);
            __nv_bfloat16 l0 = __float2bfloat16_rn(v.x - __bfloat162float(h0));
            __nv_bfloat16 l1 = __float2bfloat16_rn(v.y - __bfloat162float(h1));
            __nv_bfloat16 l2 = __float2bfloat16_rn(v.z - __bfloat162float(h2));
            __nv_bfloat16 l3 = __float2bfloat16_rn(v.w - __bfloat162float(h3));
            uint32_t hA = (uint32_t)__bfloat16_as_ushort(h0) | ((uint32_t)__bfloat16_as_ushort(h1) << 16);
            uint32_t hB = (uint32_t)__bfloat16_as_ushort(h2) | ((uint32_t)__bfloat16_as_ushort(h3) << 16);
            uint32_t lA = (uint32_t)__bfloat16_as_ushort(l0) | ((uint32_t)__bfloat16_as_ushort(l1) << 16);
            uint32_t lB = (uint32_t)__bfloat16_as_ushort(l2) | ((uint32_t)__bfloat16_as_ushort(l3) << 16);
            uint32_t sw = SW((uint32_t)((rb + it * 16) * 128 + f * 8));
            sts64(bb + AH_OFF + sw, hA, hB);
            sts64(bb + AL_OFF + sw, lA, lB);
        }

        // ---- issue A LDG for chunk s+1 (completes under MMA) ----
        if (s < NCHUNKS - 1) {
            const float* xg = x + m0 * KDIM + (s + 1) * KCHUNK;
#pragma unroll
            for (int it = 0; it < 8; it++)
                pf[it] = *(const float4*)(xg + (long)(rb + it * 16) * KDIM + f * 4);
        }

        if (s < NCHUNKS - 1) cp_wait<1>(); else cp_wait<0>();
        __syncthreads();

        // ---- compute: 4 k16-steps, 3 bf16 products each ----
#pragma unroll
        for (int kk = 0; kk < 4; kk++) {
            uint32_t ah[2][4], al[2][4], bh[2][4], bl[2][4];
#pragma unroll
            for (int mi = 0; mi < 2; mi++) {
                uint32_t row = m_warp + mi * 16 + (lane & 15);
                uint32_t kb  = kk * 32 + (lane >> 4) * 16;
                uint32_t off = SW(row * 128 + kb);
                ldm4(ah[mi], bb + AH_OFF + off);
                ldm4(al[mi], bb + AL_OFF + off);
            }
#pragma unroll
            for (int nq = 0; nq < 2; nq++) {
                uint32_t g = lane >> 3;
                uint32_t n = n_warp + nq * 16 + ((g >> 1) << 3) + (lane & 7);
                uint32_t kb = kk * 32 + (g & 1) * 16;
                uint32_t off = SW(n * 128 + kb);
                ldm4(bh[nq], bb + BH_OFF + off);
                ldm4(bl[nq], bb + BL_OFF + off);
            }
#pragma unroll
            for (int mi = 0; mi < 2; mi++)
#pragma unroll
                for (int nj = 0; nj < 4; nj++) {
                    const uint32_t* B1 = &bh[nj >> 1][(nj & 1) * 2];
                    const uint32_t* B2 = &bl[nj >> 1][(nj & 1) * 2];
                    mma16816(acc[mi][nj], ah[mi], B1);   // hi*hi
                    mma16816(acc[mi][nj], al[mi], B1);   // lo*hi
                    mma16816(acc[mi][nj], ah[mi], B2);   // hi*lo
                }
        }
        __syncthreads();   // all reads of this stage done before overwrite
    }

    // ---- epilogue: scale by U3[c,r], reduce 128 rows -> 64 partials ----
    float* s_u3 = (float*)dsm;                         // reuse stage memory
    const int c_base = (blockIdx.x & 3) * 128;
#pragma unroll
    for (int it = 0; it < 32; it++) {
        int idx = tid + it * 256;                      // 0..8191
        s_u3[idx] = U3[c_base * R_ + idx];
    }
    __syncthreads();

    float p[8];
#pragma unroll
    for (int j = 0; j < 8; j++) p[j] = 0.0f;
#pragma unroll
    for (int mi = 0; mi < 2; mi++)
#pragma unroll
        for (int pr = 0; pr < 2; pr++) {
            int rowl = m_warp + mi * 16 + pr * 8 + (lane >> 2);
            const float* w = s_u3 + rowl * R_;
#pragma unroll
            for (int nj = 0; nj < 4; nj++) {
                int col = n_warp + nj * 8 + (lane & 3) * 2;
                p[nj * 2 + 0] = fmaf(acc[mi][nj][pr * 2 + 0], w[col],     p[nj * 2 + 0]);
                p[nj * 2 + 1] = fmaf(acc[mi][nj][pr * 2 + 1], w[col + 1], p[nj * 2 + 1]);
            }
        }
#pragma unroll
    for (int o = 4; o < 32; o <<= 1)
#pragma unroll
        for (int j = 0; j < 8; j++)
            p[j] += __shfl_xor_sync(0xffffffffu, p[j], o);

    if (lane < 4) {
#pragma unroll
        for (int nj = 0; nj < 4; nj++) {
            int col = n_warp + nj * 8 + lane * 2;
            s_red[wid >> 1][col]     = p[nj * 2 + 0];
            s_red[wid >> 1][col + 1] = p[nj * 2 + 1];
        }
    }
    __syncthreads();
    if (tid < R_)
        g_part[blockIdx.x * R_ + tid] =
            s_red[0][tid] + s_red[1][tid] + s_red[2][tid] + s_red[3][tid];
}

// ===========================================================================
// Kernel 2: out[b,cls] = sum_r (sum_j part[4b+j,r]) * lam[r] * U4[cls,r]
// ===========================================================================
__global__ __launch_bounds__(256) void out_k(const float* __restrict__ lam,
                                             const float* __restrict__ U4,
                                             float* __restrict__ out) {
    const int b = blockIdx.x;
    const int tid = threadIdx.x;
    __shared__ float u[R_];
    if (tid < R_) {
        float s = g_part[(b * 4 + 0) * R_ + tid] + g_part[(b * 4 + 1) * R_ + tid]
                + g_part[(b * 4 + 2) * R_ + tid] + g_part[(b * 4 + 3) * R_ + tid];
        u[tid] = s * lam[tid];
    }
    __syncthreads();
    for (int cls = tid; cls < CLS_; cls += 256) {
        const float4* up = (const float4*)(U4 + cls * R_);
        float s = 0.0f;
#pragma unroll
        for (int j = 0; j < 16; j++) {
            float4 v = up[j];
            s = fmaf(u[j * 4 + 0], v.x, s);
            s = fmaf(u[j * 4 + 1], v.y, s);
            s = fmaf(u[j * 4 + 2], v.z, s);
            s = fmaf(u[j * 4 + 3], v.w, s);
        }
        out[b * CLS_ + cls] = s;
    }
}

// ===========================================================================
extern "C" void kernel_launch(void* const* d_in, const int* in_sizes, int n_in,
                              void* d_out, int out_size) {
    const float* x   = (const float*)d_in[0];   // (B, C, W, H)
    const float* U1  = (const float*)d_in[1];   // (H, R)
    const float* U2  = (const float*)d_in[2];   // (W, R)
    const float* U3  = (const float*)d_in[3];   // (C, R)
    const float* U4  = (const float*)d_in[4];   // (CLS, R)
    const float* lam = (const float*)d_in[5];   // (R,)
    float* out = (float*)d_out;                 // (B, CLS)

    cudaFuncSetAttribute(gemm_k, cudaFuncAttributeMaxDynamicSharedMemorySize, SMEM_DYN);

    build_M<<<R_, 1024>>>(U1, U2);
    gemm_k<<<MROWS / TILE_M, 256, SMEM_DYN>>>(x, U3);
    out_k<<<B_, 256>>>(lam, U4, out);
}

// round 10
// speedup vs baseline: 4.0220x; 1.5040x over previous
#include <cuda_runtime.h>
#include <cuda_fp16.h>
#include <cstdint>

#define H_   32
#define W_   32
#define C_   512
#define CLS_ 1000
#define R_   64
#define B_   128
#define MROWS (B_ * C_)      // 65536
#define KDIM  1024           // W*H

// ---- GEMM tiling ----
#define TILE_M   128
#define KCHUNK   64          // fp16 per row = 128 B (one swizzle atom row)
#define NCHUNKS  16
// per-stage smem layout (bytes): A 16K | B 8K = 24K, x2 stages
#define A_OFF    0
#define B_OFF    16384
#define STAGE    24576
#define SMEM_DYN (2 * STAGE)   // 48 KB

#define SW(o) ((o) ^ (((o) >> 3) & 0x70))

// ---- static device scratch (no allocations allowed) ----
__device__ __align__(16) __half g_M[R_ * KDIM];   // [r][k] fp16 merged U2*U1
__device__ float g_part[512 * R_];                // per-CTA partials

// ===========================================================================
// PTX helpers — sm_80+ baseline only
// ===========================================================================
__device__ __forceinline__ uint32_t smem_u32(const void* p) {
    uint32_t a;
    asm("{ .reg .u64 t; cvta.to.shared.u64 t, %1; cvt.u32.u64 %0, t; }"
        : "=r"(a) : "l"(p));
    return a;
}
__device__ __forceinline__ void sts64(uint32_t a, uint32_t x, uint32_t y) {
    asm volatile("st.shared.v2.b32 [%0], {%1,%2};" :: "r"(a), "r"(x), "r"(y));
}
__device__ __forceinline__ void cpasync16(uint32_t dst, const void* src) {
    asm volatile("cp.async.cg.shared.global [%0], [%1], 16;"
                 :: "r"(dst), "l"(src));
}
__device__ __forceinline__ void cp_commit() {
    asm volatile("cp.async.commit_group;");
}
template <int N>
__device__ __forceinline__ void cp_wait() {
    asm volatile("cp.async.wait_group %0;" :: "n"(N));
}
__device__ __forceinline__ void ldm4(uint32_t* r, uint32_t addr) {
    asm volatile("ldmatrix.sync.aligned.m8n8.x4.shared.b16 {%0,%1,%2,%3}, [%4];"
                 : "=r"(r[0]), "=r"(r[1]), "=r"(r[2]), "=r"(r[3]) : "r"(addr));
}
__device__ __forceinline__ void mma16816(float* c, const uint32_t* a, const uint32_t* b) {
    asm volatile(
        "mma.sync.aligned.m16n8k16.row.col.f32.f16.f16.f32 "
        "{%0,%1,%2,%3}, {%4,%5,%6,%7}, {%8,%9}, {%0,%1,%2,%3};"
        : "+f"(c[0]), "+f"(c[1]), "+f"(c[2]), "+f"(c[3])
        : "r"(a[0]), "r"(a[1]), "r"(a[2]), "r"(a[3]), "r"(b[0]), "r"(b[1]));
}

// ===========================================================================
// Kernel 0: M[r][k] = fp16( U2[w,r]*U1[h,r] ),  k = w*32+h
//   grid 64 (one block per r), block 1024 — coalesced writes
// ===========================================================================
__global__ __launch_bounds__(1024) void build_M(const float* __restrict__ U1,
                                                const float* __restrict__ U2) {
    __shared__ float su1[32], su2[32];
    const int r = blockIdx.x;
    if (threadIdx.x < 32)       su1[threadIdx.x]      = U1[threadIdx.x * R_ + r];
    else if (threadIdx.x < 64)  su2[threadIdx.x - 32] = U2[(threadIdx.x - 32) * R_ + r];
    __syncthreads();
    const int k = threadIdx.x;
    g_M[r * KDIM + k] = __float2half_rn(su2[k >> 5] * su1[k & 31]);
}

// ===========================================================================
// Kernel 1: pipelined fp16 mma.sync GEMM (128x64 tile, K=1024) + fused U3
//   row-reduce.  grid 512, block 256 (8 warps: 4m x 2n), dyn smem 48K
// ===========================================================================
__global__ __launch_bounds__(256, 2) void gemm_k(const float* __restrict__ x,
                                                 const float* __restrict__ U3) {
    extern __shared__ char dsm[];
    __shared__ float s_red[4][R_];

    const int tid  = threadIdx.x;
    const int wid  = tid >> 5;
    const int lane = tid & 31;
    const int m_warp = (wid >> 1) * 32;   // 0,32,64,96
    const int n_warp = (wid & 1) * 32;    // 0,32
    const long m0 = (long)blockIdx.x * TILE_M;

    const uint32_t sb = smem_u32(dsm);

    // B cp.async mapping: 512 16B-slots, 2 per thread
    const int bn = tid >> 3;            // 0..31 (rows bn and bn+32)
    const int bj = tid & 7;             // 16B slot within 128B row

    // A prefetch mapping: rows rb + it*16, cols f*4..f*4+3
    const int rb = tid >> 4;            // 0..15
    const int f  = tid & 15;            // 0..15

    float acc[2][4][4];
#pragma unroll
    for (int i = 0; i < 2; i++)
#pragma unroll
        for (int j = 0; j < 4; j++)
#pragma unroll
            for (int e = 0; e < 4; e++) acc[i][j][e] = 0.0f;

    // ---- prologue: B chunk 0 via cp.async, A chunk 0 into registers ----
    {
#pragma unroll
        for (int it = 0; it < 2; it++) {
            int n = bn + it * 32;
            long go = (long)n * 2048 + bj * 16;      // k0 = 0
            uint32_t sw = SW((uint32_t)(n * 128 + bj * 16));
            cpasync16(sb + B_OFF + sw, (const char*)g_M + go);
        }
        cp_commit();
    }
    float4 pf[8];
    {
        const float* xg = x + m0 * KDIM;             // k0 = 0
#pragma unroll
        for (int it = 0; it < 8; it++)
            pf[it] = *(const float4*)(xg + (long)(rb + it * 16) * KDIM + f * 4);
    }

    for (int s = 0; s < NCHUNKS; s++) {
        const uint32_t bb = sb + (uint32_t)(s & 1) * STAGE;
        const uint32_t nb = sb + (uint32_t)((s + 1) & 1) * STAGE;

        // ---- issue B cp.async for chunk s+1 ----
        if (s < NCHUNKS - 1) {
            const int k1 = (s + 1) * KCHUNK;
#pragma unroll
            for (int it = 0; it < 2; it++) {
                int n = bn + it * 32;
                long go = (long)n * 2048 + k1 * 2 + bj * 16;
                uint32_t sw = SW((uint32_t)(n * 128 + bj * 16));
                cpasync16(nb + B_OFF + sw, (const char*)g_M + go);
            }
            cp_commit();
        }

        // ---- convert prefetched A regs -> fp16 swizzled smem ----
#pragma unroll
        for (int it = 0; it < 8; it++) {
            float4 v = pf[it];
            __half h0 = __float2half_rn(v.x);
            __half h1 = __float2half_rn(v.y);
            __half h2 = __float2half_rn(v.z);
            __half h3 = __float2half_rn(v.w);
            uint32_t hA = (uint32_t)__half_as_ushort(h0) | ((uint32_t)__half_as_ushort(h1) << 16);
            uint32_t hB = (uint32_t)__half_as_ushort(h2) | ((uint32_t)__half_as_ushort(h3) << 16);
            uint32_t sw = SW((uint32_t)((rb + it * 16) * 128 + f * 8));
            sts64(bb + A_OFF + sw, hA, hB);
        }

        // ---- issue A LDG for chunk s+1 (completes under MMA) ----
        if (s < NCHUNKS - 1) {
            const float* xg = x + m0 * KDIM + (s + 1) * KCHUNK;
#pragma unroll
            for (int it = 0; it < 8; it++)
                pf[it] = *(const float4*)(xg + (long)(rb + it * 16) * KDIM + f * 4);
        }

        if (s < NCHUNKS - 1) cp_wait<1>(); else cp_wait<0>();
        __syncthreads();

        // ---- compute: 4 k16-steps ----
#pragma unroll
        for (int kk = 0; kk < 4; kk++) {
            uint32_t ah[2][4], bhh[2][4];
#pragma unroll
            for (int mi = 0; mi < 2; mi++) {
                uint32_t row = m_warp + mi * 16 + (lane & 15);
                uint32_t kb  = kk * 32 + (lane >> 4) * 16;
                ldm4(ah[mi], bb + A_OFF + SW(row * 128 + kb));
            }
#pragma unroll
            for (int nq = 0; nq < 2; nq++) {
                uint32_t g = lane >> 3;
                uint32_t n = n_warp + nq * 16 + ((g >> 1) << 3) + (lane & 7);
                uint32_t kb = kk * 32 + (g & 1) * 16;
                ldm4(bhh[nq], bb + B_OFF + SW(n * 128 + kb));
            }
#pragma unroll
            for (int mi = 0; mi < 2; mi++)
#pragma unroll
                for (int nj = 0; nj < 4; nj++)
                    mma16816(acc[mi][nj], ah[mi], &bhh[nj >> 1][(nj & 1) * 2]);
        }
        __syncthreads();   // all reads of this stage done before overwrite
    }

    // ---- epilogue: scale by U3[c,r], reduce 128 rows -> 64 partials ----
    float* s_u3 = (float*)dsm;                         // reuse stage memory (8 KB x 4)
    const int c_base = (blockIdx.x & 3) * 128;
#pragma unroll
    for (int it = 0; it < 32; it++) {
        int idx = tid + it * 256;                      // 0..8191
        s_u3[idx] = U3[c_base * R_ + idx];
    }
    __syncthreads();

    float p[8];
#pragma unroll
    for (int j = 0; j < 8; j++) p[j] = 0.0f;
#pragma unroll
    for (int mi = 0; mi < 2; mi++)
#pragma unroll
        for (int pr = 0; pr < 2; pr++) {
            int rowl = m_warp + mi * 16 + pr * 8 + (lane >> 2);
            const float* w = s_u3 + rowl * R_;
#pragma unroll
            for (int nj = 0; nj < 4; nj++) {
                int col = n_warp + nj * 8 + (lane & 3) * 2;
                p[nj * 2 + 0] = fmaf(acc[mi][nj][pr * 2 + 0], w[col],     p[nj * 2 + 0]);
                p[nj * 2 + 1] = fmaf(acc[mi][nj][pr * 2 + 1], w[col + 1], p[nj * 2 + 1]);
            }
        }
#pragma unroll
    for (int o = 4; o < 32; o <<= 1)
#pragma unroll
        for (int j = 0; j < 8; j++)
            p[j] += __shfl_xor_sync(0xffffffffu, p[j], o);

    if (lane < 4) {
#pragma unroll
        for (int nj = 0; nj < 4; nj++) {
            int col = n_warp + nj * 8 + lane * 2;
            s_red[wid >> 1][col]     = p[nj * 2 + 0];
            s_red[wid >> 1][col + 1] = p[nj * 2 + 1];
        }
    }
    __syncthreads();
    if (tid < R_)
        g_part[blockIdx.x * R_ + tid] =
            s_red[0][tid] + s_red[1][tid] + s_red[2][tid] + s_red[3][tid];
}

// ===========================================================================
// Kernel 2: out[b,cls] = sum_r (sum_j part[4b+j,r]) * lam[r] * U4[cls,r]
// ===========================================================================
__global__ __launch_bounds__(256) void out_k(const float* __restrict__ lam,
                                             const float* __restrict__ U4,
                                             float* __restrict__ out) {
    const int b = blockIdx.x;
    const int tid = threadIdx.x;
    __shared__ float u[R_];
    if (tid < R_) {
        float s = g_part[(b * 4 + 0) * R_ + tid] + g_part[(b * 4 + 1) * R_ + tid]
                + g_part[(b * 4 + 2) * R_ + tid] + g_part[(b * 4 + 3) * R_ + tid];
        u[tid] = s * lam[tid];
    }
    __syncthreads();
    for (int cls = tid; cls < CLS_; cls += 256) {
        const float4* up = (const float4*)(U4 + cls * R_);
        float s = 0.0f;
#pragma unroll
        for (int j = 0; j < 16; j++) {
            float4 v = up[j];
            s = fmaf(u[j * 4 + 0], v.x, s);
            s = fmaf(u[j * 4 + 1], v.y, s);
            s = fmaf(u[j * 4 + 2], v.z, s);
            s = fmaf(u[j * 4 + 3], v.w, s);
        }
        out[b * CLS_ + cls] = s;
    }
}

// ===========================================================================
extern "C" void kernel_launch(void* const* d_in, const int* in_sizes, int n_in,
                              void* d_out, int out_size) {
    const float* x   = (const float*)d_in[0];   // (B, C, W, H)
    const float* U1  = (const float*)d_in[1];   // (H, R)
    const float* U2  = (const float*)d_in[2];   // (W, R)
    const float* U3  = (const float*)d_in[3];   // (C, R)
    const float* U4  = (const float*)d_in[4];   // (CLS, R)
    const float* lam = (const float*)d_in[5];   // (R,)
    float* out = (float*)d_out;                 // (B, CLS)

    cudaFuncSetAttribute(gemm_k, cudaFuncAttributeMaxDynamicSharedMemorySize, SMEM_DYN);

    build_M<<<R_, 1024>>>(U1, U2);
    gemm_k<<<MROWS / TILE_M, 256, SMEM_DYN>>>(x, U3);
    out_k<<<B_, 256>>>(lam, U4, out);
}